// round 8
// baseline (speedup 1.0000x reference)
#include <cuda_runtime.h>
#include <cstdint>

#define BATCH 32768
#define IDIM  128
#define HDIM  256
#define ADIM  32
#define MT    128
#define NT    512
#define NBLK  (BATCH/MT)

// ---- packed scratch (floats) ----
#define XPK   0u
#define H0PK  4194304u
#define H1PK  12582912u
#define W0X   20971520u
#define W0H   21069824u
#define W1X   21266432u
#define W1H   21463040u
#define SCR_TOTAL 21659648u
__device__ float scr[SCR_TOTAL];

#define SMS  260                       // smem row stride (floats)
#define SMEM_MAIN (128*SMS*4)          // 133120 B

static __device__ __forceinline__ float tf32r(float x) {
    float r; asm("cvt.rna.tf32.f32 %0, %1;" : "=f"(r) : "f"(x)); return r;
}
static __device__ __forceinline__ void mma8(float c[4], const uint32_t a[4],
                                            const uint32_t b[2]) {
    asm volatile(
        "mma.sync.aligned.m16n8k8.row.col.f32.tf32.tf32.f32 "
        "{%0,%1,%2,%3},{%4,%5,%6,%7},{%8,%9},{%0,%1,%2,%3};"
        : "+f"(c[0]), "+f"(c[1]), "+f"(c[2]), "+f"(c[3])
        : "r"(a[0]), "r"(a[1]), "r"(a[2]), "r"(a[3]), "r"(b[0]), "r"(b[1]));
}
static __device__ __forceinline__ float sigf(float x) {
    return __fdividef(1.0f, 1.0f + __expf(-x));
}
static __device__ __forceinline__ float tanhff(float x) {
    float ax = fabsf(x), e = __expf(-2.0f * ax);
    return copysignf(__fdividef(1.0f - e, 1.0f + e), x);
}
static __device__ __forceinline__ float gru1(float rp, float zp, float ip,
                                             float hp, float hv) {
    float r = sigf(rp), z = sigf(zp);
    float n = tanhff(ip + r * hp);
    return n + z * (hv - n);
}

// ---------------- pre-kernel: pack weights into fragment order ----------------
__global__ void __launch_bounds__(256)
pack_w(const float* __restrict__ wih0, const float* __restrict__ whh0,
       const float* __restrict__ wih1, const float* __restrict__ whh1)
{
    int i = blockIdx.x * 256 + threadIdx.x;     // global out float4 index
    if (i >= 172032) return;
    const float* src; uint32_t base; int K; int l = i;
    if (l < 24576)                { src = wih0; base = W0X; K = 128; }
    else if ((l -= 24576) < 49152){ src = whh0; base = W0H; K = 256; }
    else if ((l -= 49152) < 49152){ src = wih1; base = W1X; K = 256; }
    else { l -= 49152;              src = whh1; base = W1H; K = 256; }
    int lane = l & 31, blk = l >> 5;
    int KB2 = K >> 4;
    int j  = blk % KB2;
    int nb = (blk / KB2) & 31;
    int g  = blk / (KB2 * 32);
    int gid = lane >> 2, tg = lane & 3;
    int row = g * 256 + nb * 8 + gid;
    const float* wr = src + (size_t)row * K + j * 16 + tg;
    float4 v;
    v.x = tf32r(wr[0]); v.y = tf32r(wr[4]);
    v.z = tf32r(wr[8]); v.w = tf32r(wr[12]);
    ((float4*)(scr + base))[l] = v;
}

// ---------------- pre-kernel: pack A-sources into fragment order ----------------
__global__ void __launch_bounds__(256)
pack_a(const float* __restrict__ x, const float* __restrict__ hin)
{
    extern __shared__ float sb[];
    int bb = blockIdx.x, m = blockIdx.y, tid = threadIdx.x;
    const float* src; uint32_t base; int K;
    if (m == 0)      { src = x;   base = XPK;  K = IDIM; }
    else if (m == 1) { src = hin; base = H0PK; K = HDIM; }
    else             { src = hin + (size_t)BATCH * HDIM; base = H1PK; K = HDIM; }
    src += (size_t)bb * 128 * K;
    const int KQ = K / 4;
    for (int i = tid; i < 128 * KQ; i += 256) {
        int r = i / KQ, c = i % KQ;
        float4 v = ((const float4*)src)[i];
        *(float4*)&sb[r * SMS + c * 4] = v;
    }
    __syncthreads();
    const int KB = K / 8;
    const int nout = 8 * KB * 32;
    float4* outp = (float4*)(scr + base) + (size_t)bb * nout;
    for (int o = tid; o < nout; o += 256) {
        int lane = o & 31, kb = (o >> 5) % KB, mb = (o >> 5) / KB;
        int gid = lane >> 2, tg = lane & 3;
        int r0 = mb * 16 + gid, k = kb * 8 + tg;
        float4 v;
        v.x = tf32r(sb[r0 * SMS + k]);
        v.y = tf32r(sb[(r0 + 8) * SMS + k]);
        v.z = tf32r(sb[r0 * SMS + k + 4]);
        v.w = tf32r(sb[(r0 + 8) * SMS + k + 4]);
        outp[o] = v;
    }
}

#define FRAG(d, v) do { d[0] = __float_as_uint((v).x); d[1] = __float_as_uint((v).y); \
                        d[2] = __float_as_uint((v).z); d[3] = __float_as_uint((v).w); } while (0)

__global__ void __launch_bounds__(NT, 1)
gru_ac_kernel(const float* __restrict__ x,    const float* __restrict__ hin,
              const float* __restrict__ bih0, const float* __restrict__ bhh0,
              const float* __restrict__ bih1, const float* __restrict__ bhh1,
              const float* __restrict__ wp,   const float* __restrict__ bp,
              const float* __restrict__ wv,   const float* __restrict__ bv,
              float* __restrict__ out)
{
    extern __shared__ float h0s[];          // 128 x SMS (tf32 copy of h0)
    const float4* S4 = (const float4*)scr;
    const int tid  = threadIdx.x;
    const int lane = tid & 31;
    const int wid  = tid >> 5;
    const int wm   = wid >> 2;
    const int wn   = wid & 3;
    const int gID  = lane >> 2;
    const int tig  = lane & 3;
    const int bb   = blockIdx.x;
    const int rowbase = bb * MT;

    float* outL  = out;
    float* outV  = out + (size_t)BATCH * ADIM;
    float* hbase = out + (size_t)BATCH * (ADIM + 1);   // [2][B][H]

    for (int layer = 0; layer < 2; ++layer) {
        const float* bih = layer ? bih1 : bih0;
        const float* bhh = layer ? bhh1 : bhh0;
        const float* asrch = hin + (size_t)layer * BATCH * HDIM
                                 + (size_t)rowbase * HDIM;
        float* hdst = hbase + (size_t)layer * BATCH * HDIM
                            + (size_t)rowbase * HDIM;

        for (int q = 0; q < 4; ++q) {
            float aR[2][2][4], aZ[2][2][4], aI[2][2][4], aH[2][2][4];
            #pragma unroll
            for (int t = 0; t < 2; ++t)
                #pragma unroll
                for (int s = 0; s < 2; ++s)
                    #pragma unroll
                    for (int k = 0; k < 4; ++k) {
                        aR[t][s][k] = 0.f; aZ[t][s][k] = 0.f;
                        aI[t][s][k] = 0.f; aH[t][s][k] = 0.f;
                    }
            const int nb0 = q * 8 + wn * 2;

            // gmem-fragment phase with 1-deep register double buffer
            auto phase_pk = [&](uint32_t a_base4, int KB2a, uint32_t w_base4,
                                int KB2w, float (*accN)[2][4]) {
                const int KBa = KB2a * 2;
                uint32_t ia0 = a_base4 + (uint32_t)(bb * 8 + wm * 2) * KBa * 32 + lane;
                uint32_t ia1 = ia0 + KBa * 32;
                uint32_t iw[3][2];
                #pragma unroll
                for (int g = 0; g < 3; ++g)
                    #pragma unroll
                    for (int s = 0; s < 2; ++s)
                        iw[g][s] = w_base4
                            + (uint32_t)((g * 32 + nb0 + s) * KB2w) * 32 + lane;
                float4 ac[4], wc[3][2];
                ac[0] = S4[ia0];      ac[1] = S4[ia0 + 32];
                ac[2] = S4[ia1];      ac[3] = S4[ia1 + 32];
                #pragma unroll
                for (int g = 0; g < 3; ++g)
                    #pragma unroll
                    for (int s = 0; s < 2; ++s)
                        wc[g][s] = S4[iw[g][s]];
                #pragma unroll 4
                for (int j = 0; j < KB2a; ++j) {
                    float4 an[4], wx[3][2];
                    if (j + 1 < KB2a) {
                        an[0] = S4[ia0 + (2 * j + 2) * 32];
                        an[1] = S4[ia0 + (2 * j + 3) * 32];
                        an[2] = S4[ia1 + (2 * j + 2) * 32];
                        an[3] = S4[ia1 + (2 * j + 3) * 32];
                        #pragma unroll
                        for (int g = 0; g < 3; ++g)
                            #pragma unroll
                            for (int s = 0; s < 2; ++s)
                                wx[g][s] = S4[iw[g][s] + (j + 1) * 32];
                    }
                    uint32_t af[2][2][4];
                    FRAG(af[0][0], ac[0]); FRAG(af[0][1], ac[1]);
                    FRAG(af[1][0], ac[2]); FRAG(af[1][1], ac[3]);
                    #pragma unroll
                    for (int s = 0; s < 2; ++s) {
                        uint32_t bR[2][2], bZ[2][2], bN[2][2];
                        bR[0][0] = __float_as_uint(wc[0][s].x);
                        bR[0][1] = __float_as_uint(wc[0][s].y);
                        bR[1][0] = __float_as_uint(wc[0][s].z);
                        bR[1][1] = __float_as_uint(wc[0][s].w);
                        bZ[0][0] = __float_as_uint(wc[1][s].x);
                        bZ[0][1] = __float_as_uint(wc[1][s].y);
                        bZ[1][0] = __float_as_uint(wc[1][s].z);
                        bZ[1][1] = __float_as_uint(wc[1][s].w);
                        bN[0][0] = __float_as_uint(wc[2][s].x);
                        bN[0][1] = __float_as_uint(wc[2][s].y);
                        bN[1][0] = __float_as_uint(wc[2][s].z);
                        bN[1][1] = __float_as_uint(wc[2][s].w);
                        #pragma unroll
                        for (int h = 0; h < 2; ++h)
                            #pragma unroll
                            for (int t = 0; t < 2; ++t) {
                                mma8(aR[t][s], af[t][h], bR[h]);
                                mma8(aZ[t][s], af[t][h], bZ[h]);
                                mma8(accN[t][s], af[t][h], bN[h]);
                            }
                    }
                    #pragma unroll
                    for (int i = 0; i < 4; ++i) ac[i] = an[i];
                    #pragma unroll
                    for (int g = 0; g < 3; ++g)
                        #pragma unroll
                        for (int s = 0; s < 2; ++s)
                            wc[g][s] = wx[g][s];
                }
            };

            // smem-A phase (layer 1 x-part): prefetch W, A from smem (29cyc)
            auto phase_sm = [&](uint32_t w_base4, float (*accN)[2][4]) {
                uint32_t iw[3][2];
                #pragma unroll
                for (int g = 0; g < 3; ++g)
                    #pragma unroll
                    for (int s = 0; s < 2; ++s)
                        iw[g][s] = w_base4
                            + (uint32_t)((g * 32 + nb0 + s) * 16) * 32 + lane;
                float4 wc[3][2];
                #pragma unroll
                for (int g = 0; g < 3; ++g)
                    #pragma unroll
                    for (int s = 0; s < 2; ++s)
                        wc[g][s] = S4[iw[g][s]];
                #pragma unroll 4
                for (int j = 0; j < 16; ++j) {
                    float4 wx[3][2];
                    if (j + 1 < 16) {
                        #pragma unroll
                        for (int g = 0; g < 3; ++g)
                            #pragma unroll
                            for (int s = 0; s < 2; ++s)
                                wx[g][s] = S4[iw[g][s] + (j + 1) * 32];
                    }
                    uint32_t af[2][2][4];
                    #pragma unroll
                    for (int t = 0; t < 2; ++t) {
                        const float* hp = &h0s[(wm * 32 + t * 16 + gID) * SMS];
                        #pragma unroll
                        for (int h = 0; h < 2; ++h) {
                            int k = (2 * j + h) * 8 + tig;
                            af[t][h][0] = __float_as_uint(hp[k]);
                            af[t][h][1] = __float_as_uint(hp[8 * SMS + k]);
                            af[t][h][2] = __float_as_uint(hp[k + 4]);
                            af[t][h][3] = __float_as_uint(hp[8 * SMS + k + 4]);
                        }
                    }
                    #pragma unroll
                    for (int s = 0; s < 2; ++s) {
                        uint32_t bR[2][2], bZ[2][2], bN[2][2];
                        bR[0][0] = __float_as_uint(wc[0][s].x);
                        bR[0][1] = __float_as_uint(wc[0][s].y);
                        bR[1][0] = __float_as_uint(wc[0][s].z);
                        bR[1][1] = __float_as_uint(wc[0][s].w);
                        bZ[0][0] = __float_as_uint(wc[1][s].x);
                        bZ[0][1] = __float_as_uint(wc[1][s].y);
                        bZ[1][0] = __float_as_uint(wc[1][s].z);
                        bZ[1][1] = __float_as_uint(wc[1][s].w);
                        bN[0][0] = __float_as_uint(wc[2][s].x);
                        bN[0][1] = __float_as_uint(wc[2][s].y);
                        bN[1][0] = __float_as_uint(wc[2][s].z);
                        bN[1][1] = __float_as_uint(wc[2][s].w);
                        #pragma unroll
                        for (int h = 0; h < 2; ++h)
                            #pragma unroll
                            for (int t = 0; t < 2; ++t) {
                                mma8(aR[t][s], af[t][h], bR[h]);
                                mma8(aZ[t][s], af[t][h], bZ[h]);
                                mma8(accN[t][s], af[t][h], bN[h]);
                            }
                    }
                    #pragma unroll
                    for (int g = 0; g < 3; ++g)
                        #pragma unroll
                        for (int s = 0; s < 2; ++s)
                            wc[g][s] = wx[g][s];
                }
            };

            if (layer == 0) {
                phase_pk(XPK / 4,  8,  W0X / 4, 8,  aI);   // x part (K=128)
                phase_pk(H0PK / 4, 16, W0H / 4, 16, aH);   // h part (K=256)
            } else {
                phase_sm(W1X / 4, aI);                      // h0 (smem) part
                phase_pk(H1PK / 4, 16, W1H / 4, 16, aH);   // h part (K=256)
            }

            // ---- elementwise GRU gates ----
            #pragma unroll
            for (int s = 0; s < 2; ++s) {
                const int c = q * 64 + wn * 16 + s * 8 + tig * 2;
                float2 bi0 = *(const float2*)&bih[c];
                float2 bh0 = *(const float2*)&bhh[c];
                float2 bi1 = *(const float2*)&bih[256 + c];
                float2 bh1 = *(const float2*)&bhh[256 + c];
                float2 bIv = *(const float2*)&bih[512 + c];
                float2 bHv = *(const float2*)&bhh[512 + c];
                float2 bRv = make_float2(bi0.x + bh0.x, bi0.y + bh0.y);
                float2 bZv = make_float2(bi1.x + bh1.x, bi1.y + bh1.y);
                #pragma unroll
                for (int t = 0; t < 2; ++t) {
                    const int ra = wm * 32 + t * 16 + gID;
                    const int rb = ra + 8;
                    float2 ha = *(const float2*)&asrch[(size_t)ra * HDIM + c];
                    float2 hb = *(const float2*)&asrch[(size_t)rb * HDIM + c];
                    float2 oa, ob;
                    oa.x = gru1(aR[t][s][0] + bRv.x, aZ[t][s][0] + bZv.x,
                                aI[t][s][0] + bIv.x, aH[t][s][0] + bHv.x, ha.x);
                    oa.y = gru1(aR[t][s][1] + bRv.y, aZ[t][s][1] + bZv.y,
                                aI[t][s][1] + bIv.y, aH[t][s][1] + bHv.y, ha.y);
                    ob.x = gru1(aR[t][s][2] + bRv.x, aZ[t][s][2] + bZv.x,
                                aI[t][s][2] + bIv.x, aH[t][s][2] + bHv.x, hb.x);
                    ob.y = gru1(aR[t][s][3] + bRv.y, aZ[t][s][3] + bZv.y,
                                aI[t][s][3] + bIv.y, aH[t][s][3] + bHv.y, hb.y);
                    *(float2*)&hdst[(size_t)ra * HDIM + c] = oa;
                    *(float2*)&hdst[(size_t)rb * HDIM + c] = ob;
                    if (layer == 0) {
                        float2 ta = make_float2(tf32r(oa.x), tf32r(oa.y));
                        float2 tb = make_float2(tf32r(ob.x), tf32r(ob.y));
                        *(float2*)&h0s[ra * SMS + c] = ta;
                        *(float2*)&h0s[rb * SMS + c] = tb;
                    }
                }
            }
        }
        __syncthreads();   // h0s (and hdst) complete before layer 1 / heads
    }

    // heads: logits = h1 @ w_p^T + b_p ; value = h1 @ w_v^T + b_v
    {
        const int row = tid >> 2;
        const int qq  = tid & 3;
        const float* h1r = hbase + (size_t)BATCH * HDIM
                                 + (size_t)(rowbase + row) * HDIM;
        float acc[8];
        #pragma unroll
        for (int a = 0; a < 8; ++a) acc[a] = bp[qq * 8 + a];
        float av = bv[0];
        const float4* h4 = (const float4*)h1r;
        for (int kb = 0; kb < HDIM / 4; ++kb) {
            float4 hv = h4[kb];
            #pragma unroll
            for (int a = 0; a < 8; ++a) {
                const float4 wq =
                    *(const float4*)&wp[(qq * 8 + a) * HDIM + kb * 4];
                acc[a] += hv.x * wq.x + hv.y * wq.y + hv.z * wq.z + hv.w * wq.w;
            }
            if (qq == 0) {
                const float4 wq = *(const float4*)&wv[kb * 4];
                av += hv.x * wq.x + hv.y * wq.y + hv.z * wq.z + hv.w * wq.w;
            }
        }
        #pragma unroll
        for (int a = 0; a < 8; ++a)
            outL[(size_t)(rowbase + row) * ADIM + qq * 8 + a] = acc[a];
        if (qq == 0) outV[rowbase + row] = av;
    }
}

extern "C" void kernel_launch(void* const* d_in, const int* in_sizes, int n_in,
                              void* d_out, int out_size) {
    const float* x    = (const float*)d_in[0];
    const float* hin  = (const float*)d_in[1];
    const float* wih0 = (const float*)d_in[2];
    const float* whh0 = (const float*)d_in[3];
    const float* bih0 = (const float*)d_in[4];
    const float* bhh0 = (const float*)d_in[5];
    const float* wih1 = (const float*)d_in[6];
    const float* whh1 = (const float*)d_in[7];
    const float* bih1 = (const float*)d_in[8];
    const float* bhh1 = (const float*)d_in[9];
    const float* wp   = (const float*)d_in[10];
    const float* bp   = (const float*)d_in[11];
    const float* wv   = (const float*)d_in[12];
    const float* bv   = (const float*)d_in[13];
    float* out = (float*)d_out;

    pack_w<<<672, 256>>>(wih0, whh0, wih1, whh1);

    cudaFuncSetAttribute(pack_a,
                         cudaFuncAttributeMaxDynamicSharedMemorySize, SMEM_MAIN);
    pack_a<<<dim3(NBLK, 3), 256, SMEM_MAIN>>>(x, hin);

    cudaFuncSetAttribute(gru_ac_kernel,
                         cudaFuncAttributeMaxDynamicSharedMemorySize, SMEM_MAIN);
    gru_ac_kernel<<<NBLK, NT, SMEM_MAIN>>>(x, hin, bih0, bhh0, bih1, bhh1,
                                           wp, bp, wv, bv, out);
}

// round 9
// speedup vs baseline: 1.2104x; 1.2104x over previous
#include <cuda_runtime.h>
#include <cstdint>

#define BATCH 32768
#define IDIM  128
#define HDIM  256
#define ADIM  32
#define MT    64
#define NT    256
#define NBLK  (BATCH/MT)

// ---- packed scratch (floats) ----
#define XPK   0u
#define H0PK  4194304u
#define H1PK  12582912u
#define W0X   20971520u
#define W0H   21069824u
#define W1X   21266432u
#define W1H   21463040u
#define H0X   21659648u
#define SCR_TOTAL 30048256u
__device__ float scr[SCR_TOTAL];

static __device__ __forceinline__ float tf32r(float x) {
    float r; asm("cvt.rna.tf32.f32 %0, %1;" : "=f"(r) : "f"(x)); return r;
}
static __device__ __forceinline__ void mma8(float c[4], const uint32_t a[4],
                                            const uint32_t b[2]) {
    asm volatile(
        "mma.sync.aligned.m16n8k8.row.col.f32.tf32.tf32.f32 "
        "{%0,%1,%2,%3},{%4,%5,%6,%7},{%8,%9},{%0,%1,%2,%3};"
        : "+f"(c[0]), "+f"(c[1]), "+f"(c[2]), "+f"(c[3])
        : "r"(a[0]), "r"(a[1]), "r"(a[2]), "r"(a[3]), "r"(b[0]), "r"(b[1]));
}
static __device__ __forceinline__ float sigf(float x) {
    return __fdividef(1.0f, 1.0f + __expf(-x));
}
static __device__ __forceinline__ float tanhff(float x) {
    float ax = fabsf(x), e = __expf(-2.0f * ax);
    return copysignf(__fdividef(1.0f - e, 1.0f + e), x);
}
static __device__ __forceinline__ float gru1(float rp, float zp, float ip,
                                             float hp, float hv) {
    float r = sigf(rp), z = sigf(zp);
    float n = tanhff(ip + r * hp);
    return n + z * (hv - n);
}

// ---------------- pre-kernel: pack weights into fragment order ----------------
__global__ void __launch_bounds__(256)
pack_w(const float* __restrict__ wih0, const float* __restrict__ whh0,
       const float* __restrict__ wih1, const float* __restrict__ whh1)
{
    int i = blockIdx.x * 256 + threadIdx.x;     // global out float4 index
    if (i >= 172032) return;
    const float* src; uint32_t base; int K; int l = i;
    if (l < 24576)                { src = wih0; base = W0X; K = 128; }
    else if ((l -= 24576) < 49152){ src = whh0; base = W0H; K = 256; }
    else if ((l -= 49152) < 49152){ src = wih1; base = W1X; K = 256; }
    else { l -= 49152;              src = whh1; base = W1H; K = 256; }
    int lane = l & 31, blk = l >> 5;
    int KB2 = K >> 4;
    int j  = blk % KB2;
    int nb = (blk / KB2) & 31;
    int g  = blk / (KB2 * 32);
    int gid = lane >> 2, tg = lane & 3;
    int row = g * 256 + nb * 8 + gid;
    const float* wr = src + (size_t)row * K + j * 16 + tg;
    float4 v;
    v.x = tf32r(wr[0]); v.y = tf32r(wr[4]);
    v.z = tf32r(wr[8]); v.w = tf32r(wr[12]);
    ((float4*)(scr + base))[l] = v;
}

// ---------------- pre-kernel: pack A-sources into fragment order ----------------
#define SMS 260
__global__ void __launch_bounds__(256)
pack_a(const float* __restrict__ x, const float* __restrict__ hin)
{
    extern __shared__ float sb[];
    int bb = blockIdx.x, m = blockIdx.y, tid = threadIdx.x;
    const float* src; uint32_t base; int K;
    if (m == 0)      { src = x;   base = XPK;  K = IDIM; }
    else if (m == 1) { src = hin; base = H0PK; K = HDIM; }
    else             { src = hin + (size_t)BATCH * HDIM; base = H1PK; K = HDIM; }
    src += (size_t)bb * 128 * K;
    const int KQ = K / 4;
    for (int i = tid; i < 128 * KQ; i += 256) {
        int r = i / KQ, c = i % KQ;
        float4 v = ((const float4*)src)[i];
        *(float4*)&sb[r * SMS + c * 4] = v;
    }
    __syncthreads();
    const int KB = K / 8;
    const int nout = 8 * KB * 32;
    float4* outp = (float4*)(scr + base) + (size_t)bb * nout;
    for (int o = tid; o < nout; o += 256) {
        int lane = o & 31, kb = (o >> 5) % KB, mb = (o >> 5) / KB;
        int gid = lane >> 2, tg = lane & 3;
        int r0 = mb * 16 + gid, k = kb * 8 + tg;
        float4 v;
        v.x = tf32r(sb[r0 * SMS + k]);
        v.y = tf32r(sb[(r0 + 8) * SMS + k]);
        v.z = tf32r(sb[r0 * SMS + k + 4]);
        v.w = tf32r(sb[(r0 + 8) * SMS + k + 4]);
        outp[o] = v;
    }
}

#define FRAG(d, v) do { d[0] = __float_as_uint((v).x); d[1] = __float_as_uint((v).y); \
                        d[2] = __float_as_uint((v).z); d[3] = __float_as_uint((v).w); } while (0)

__global__ void __launch_bounds__(NT, 2)
gru_ac_kernel(const float* __restrict__ x,    const float* __restrict__ hin,
              const float* __restrict__ bih0, const float* __restrict__ bhh0,
              const float* __restrict__ bih1, const float* __restrict__ bhh1,
              const float* __restrict__ wp,   const float* __restrict__ bp,
              const float* __restrict__ wv,   const float* __restrict__ bv,
              float* __restrict__ out)
{
    const float4* S4 = (const float4*)scr;
    float* h0x = scr + H0X;
    const int tid  = threadIdx.x;
    const int lane = tid & 31;
    const int wid  = tid >> 5;
    const int wm   = wid >> 2;     // 0..1
    const int wn   = wid & 3;      // 0..3
    const int gID  = lane >> 2;
    const int tig  = lane & 3;
    const int bb   = blockIdx.x;
    const int rowbase = bb * MT;

    float* outL  = out;
    float* outV  = out + (size_t)BATCH * ADIM;
    float* hbase = out + (size_t)BATCH * (ADIM + 1);   // [2][B][H]

    for (int layer = 0; layer < 2; ++layer) {
        const float* bih = layer ? bih1 : bih0;
        const float* bhh = layer ? bhh1 : bhh0;
        const float* asrch = hin + (size_t)layer * BATCH * HDIM
                                 + (size_t)rowbase * HDIM;
        float* hdst = hbase + (size_t)layer * BATCH * HDIM
                            + (size_t)rowbase * HDIM;

        for (int q = 0; q < 4; ++q) {
            float aR[2][2][4], aZ[2][2][4], aI[2][2][4], aH[2][2][4];
            #pragma unroll
            for (int t = 0; t < 2; ++t)
                #pragma unroll
                for (int s = 0; s < 2; ++s)
                    #pragma unroll
                    for (int k = 0; k < 4; ++k) {
                        aR[t][s][k] = 0.f; aZ[t][s][k] = 0.f;
                        aI[t][s][k] = 0.f; aH[t][s][k] = 0.f;
                    }
            const int nb0 = q * 8 + wn * 2;

            // gmem-fragment GEMM phase (R7-style, no reg double-buffer)
            auto phase_pk = [&](uint32_t a_base4, int KB2a, uint32_t w_base4,
                                int KB2w, float (*accN)[2][4]) {
                const int KBa = KB2a * 2;
                uint32_t ia0 = a_base4
                    + (uint32_t)(bb * 4 + wm * 2) * KBa * 32 + lane;
                uint32_t ia1 = ia0 + KBa * 32;
                uint32_t iw[3][2];
                #pragma unroll
                for (int g = 0; g < 3; ++g)
                    #pragma unroll
                    for (int s = 0; s < 2; ++s)
                        iw[g][s] = w_base4
                            + (uint32_t)((g * 32 + nb0 + s) * KB2w) * 32 + lane;
                for (int j = 0; j < KB2a; ++j) {
                    float4 a00 = S4[ia0 + (2 * j) * 32];
                    float4 a01 = S4[ia0 + (2 * j + 1) * 32];
                    float4 a10 = S4[ia1 + (2 * j) * 32];
                    float4 a11 = S4[ia1 + (2 * j + 1) * 32];
                    float4 w_[3][2];
                    #pragma unroll
                    for (int g = 0; g < 3; ++g)
                        #pragma unroll
                        for (int s = 0; s < 2; ++s)
                            w_[g][s] = S4[iw[g][s] + j * 32];
                    uint32_t af[2][2][4];
                    FRAG(af[0][0], a00); FRAG(af[0][1], a01);
                    FRAG(af[1][0], a10); FRAG(af[1][1], a11);
                    #pragma unroll
                    for (int s = 0; s < 2; ++s) {
                        uint32_t bR[2][2], bZ[2][2], bN[2][2];
                        bR[0][0] = __float_as_uint(w_[0][s].x);
                        bR[0][1] = __float_as_uint(w_[0][s].y);
                        bR[1][0] = __float_as_uint(w_[0][s].z);
                        bR[1][1] = __float_as_uint(w_[0][s].w);
                        bZ[0][0] = __float_as_uint(w_[1][s].x);
                        bZ[0][1] = __float_as_uint(w_[1][s].y);
                        bZ[1][0] = __float_as_uint(w_[1][s].z);
                        bZ[1][1] = __float_as_uint(w_[1][s].w);
                        bN[0][0] = __float_as_uint(w_[2][s].x);
                        bN[0][1] = __float_as_uint(w_[2][s].y);
                        bN[1][0] = __float_as_uint(w_[2][s].z);
                        bN[1][1] = __float_as_uint(w_[2][s].w);
                        #pragma unroll
                        for (int h = 0; h < 2; ++h)
                            #pragma unroll
                            for (int t = 0; t < 2; ++t) {
                                mma8(aR[t][s], af[t][h], bR[h]);
                                mma8(aZ[t][s], af[t][h], bZ[h]);
                                mma8(accN[t][s], af[t][h], bN[h]);
                            }
                    }
                }
            };

            if (layer == 0) {
                phase_pk(XPK / 4,  8,  W0X / 4, 8,  aI);   // x part (K=128)
                phase_pk(H0PK / 4, 16, W0H / 4, 16, aH);   // h part (K=256)
            } else {
                phase_pk(H0X / 4,  16, W1X / 4, 16, aI);   // h0 (packed) part
                phase_pk(H1PK / 4, 16, W1H / 4, 16, aH);   // h part (K=256)
            }

            // ---- elementwise GRU gates ----
            #pragma unroll
            for (int s = 0; s < 2; ++s) {
                const int c = q * 64 + wn * 16 + s * 8 + tig * 2;
                float2 bi0 = *(const float2*)&bih[c];
                float2 bh0 = *(const float2*)&bhh[c];
                float2 bi1 = *(const float2*)&bih[256 + c];
                float2 bh1 = *(const float2*)&bhh[256 + c];
                float2 bIv = *(const float2*)&bih[512 + c];
                float2 bHv = *(const float2*)&bhh[512 + c];
                float2 bRv = make_float2(bi0.x + bh0.x, bi0.y + bh0.y);
                float2 bZv = make_float2(bi1.x + bh1.x, bi1.y + bh1.y);
                #pragma unroll
                for (int t = 0; t < 2; ++t) {
                    const int ra = wm * 32 + t * 16 + gID;
                    const int rb = ra + 8;
                    float2 ha = *(const float2*)&asrch[(size_t)ra * HDIM + c];
                    float2 hb = *(const float2*)&asrch[(size_t)rb * HDIM + c];
                    float2 oa, ob;
                    oa.x = gru1(aR[t][s][0] + bRv.x, aZ[t][s][0] + bZv.x,
                                aI[t][s][0] + bIv.x, aH[t][s][0] + bHv.x, ha.x);
                    oa.y = gru1(aR[t][s][1] + bRv.y, aZ[t][s][1] + bZv.y,
                                aI[t][s][1] + bIv.y, aH[t][s][1] + bHv.y, ha.y);
                    ob.x = gru1(aR[t][s][2] + bRv.x, aZ[t][s][2] + bZv.x,
                                aI[t][s][2] + bIv.x, aH[t][s][2] + bHv.x, hb.x);
                    ob.y = gru1(aR[t][s][3] + bRv.y, aZ[t][s][3] + bZv.y,
                                aI[t][s][3] + bIv.y, aH[t][s][3] + bHv.y, hb.y);
                    *(float2*)&hdst[(size_t)ra * HDIM + c] = oa;
                    *(float2*)&hdst[(size_t)rb * HDIM + c] = ob;
                    if (layer == 0) {
                        // fragment-packed tf32 h0 store:
                        // value A[r][k]: comp = (r%16>=8) + 2*(k%8>=4),
                        // lane = (r%8)*4 + (k%4); here r%8=gID, rhi: ra->0, rb->1
                        const int mbg = bb * 4 + wm * 2 + t;
                        const int kb  = q * 8 + wn * 2 + s;
                        const int khi = tig >> 1;
                        const int tg0 = (tig & 1) * 2;
                        uint32_t fi = (uint32_t)(((mbg * 32 + kb) * 32
                                     + gID * 4 + tg0) * 4 + 2 * khi);
                        float2 v0 = make_float2(tf32r(oa.x), tf32r(ob.x));
                        float2 v1 = make_float2(tf32r(oa.y), tf32r(ob.y));
                        *(float2*)&h0x[fi]     = v0;   // col k0
                        *(float2*)&h0x[fi + 4] = v1;   // col k0+1 (next lane)
                    }
                }
            }
        }
        __syncthreads();   // h0x (gmem) + hdst visible to all warps of this CTA
    }

    // heads: logits = h1 @ w_p^T + b_p ; value = h1 @ w_v^T + b_v
    {
        const int row = tid >> 2;              // 0..63
        const int qq  = tid & 3;
        const float* h1r = hbase + (size_t)BATCH * HDIM
                                 + (size_t)(rowbase + row) * HDIM;
        float acc[8];
        #pragma unroll
        for (int a = 0; a < 8; ++a) acc[a] = bp[qq * 8 + a];
        float av = bv[0];
        const float4* h4 = (const float4*)h1r;
        for (int kb = 0; kb < HDIM / 4; ++kb) {
            float4 hv = h4[kb];
            #pragma unroll
            for (int a = 0; a < 8; ++a) {
                const float4 wq =
                    *(const float4*)&wp[(qq * 8 + a) * HDIM + kb * 4];
                acc[a] += hv.x * wq.x + hv.y * wq.y + hv.z * wq.z + hv.w * wq.w;
            }
            if (qq == 0) {
                const float4 wq = *(const float4*)&wv[kb * 4];
                av += hv.x * wq.x + hv.y * wq.y + hv.z * wq.z + hv.w * wq.w;
            }
        }
        #pragma unroll
        for (int a = 0; a < 8; ++a)
            outL[(size_t)(rowbase + row) * ADIM + qq * 8 + a] = acc[a];
        if (qq == 0) outV[rowbase + row] = av;
    }
}

extern "C" void kernel_launch(void* const* d_in, const int* in_sizes, int n_in,
                              void* d_out, int out_size) {
    const float* x    = (const float*)d_in[0];
    const float* hin  = (const float*)d_in[1];
    const float* wih0 = (const float*)d_in[2];
    const float* whh0 = (const float*)d_in[3];
    const float* bih0 = (const float*)d_in[4];
    const float* bhh0 = (const float*)d_in[5];
    const float* wih1 = (const float*)d_in[6];
    const float* whh1 = (const float*)d_in[7];
    const float* bih1 = (const float*)d_in[8];
    const float* bhh1 = (const float*)d_in[9];
    const float* wp   = (const float*)d_in[10];
    const float* bp   = (const float*)d_in[11];
    const float* wv   = (const float*)d_in[12];
    const float* bv   = (const float*)d_in[13];
    float* out = (float*)d_out;

    pack_w<<<672, 256>>>(wih0, whh0, wih1, whh1);

    cudaFuncSetAttribute(pack_a,
                         cudaFuncAttributeMaxDynamicSharedMemorySize, 128 * SMS * 4);
    pack_a<<<dim3(BATCH / 128, 3), 256, 128 * SMS * 4>>>(x, hin);

    gru_ac_kernel<<<NBLK, NT>>>(x, hin, bih0, bhh0, bih1, bhh1,
                                wp, bp, wv, bv, out);
}